// round 11
// baseline (speedup 1.0000x reference)
#include <cuda_runtime.h>
#include <cuda_bf16.h>
#include <cstdint>

#define Bb 64
#define Tt 512
#define Ii 1024
#define Hh 1024

#define RNN_CTAS 128
// rnn smem floats: Wsh 32768 + hs 8*4*256=8192 + red 8*256=2048 = 43008 (168KB)
#define RNN_SMEM_BYTES ((32768 + 8192 + 2048) * 4)

__device__ __align__(16) float g_Wih[Hh * Ii];
__device__ __align__(16) float g_bias[Hh];
__device__ __align__(16) float g_hT[2 * Hh * Bb];   // double-buffered h, [k][b]
__device__ unsigned g_cnt[256];    // 8 barrier groups, stride 32 (128B apart)
__device__ unsigned g_done[32];
__device__ unsigned g_dummy;

typedef unsigned long long u64t;

__device__ __forceinline__ u64t pack2(float x, float y) {
    u64t r; asm("mov.b64 %0, {%1,%2};" : "=l"(r) : "f"(x), "f"(y)); return r;
}
__device__ __forceinline__ u64t fma2(u64t a, u64t b, u64t c) {
    u64t d; asm("fma.rn.f32x2 %0, %1, %2, %3;" : "=l"(d) : "l"(a), "l"(b), "l"(c)); return d;
}
__device__ __forceinline__ u64t add2(u64t a, u64t b) {
    u64t d; asm("add.rn.f32x2 %0, %1, %2;" : "=l"(d) : "l"(a), "l"(b)); return d;
}
__device__ __forceinline__ void cpasync16(uint32_t dst, const void* src) {
    asm volatile("cp.async.cg.shared.global [%0], [%1], 16;" :: "r"(dst), "l"(src));
}
#define CP_COMMIT() asm volatile("cp.async.commit_group;")

__device__ __forceinline__ void arrive_release(unsigned* p) {
    asm volatile("red.release.gpu.global.add.u32 [%0], %1;" :: "l"(p), "r"(1u) : "memory");
}
__device__ __forceinline__ unsigned ld_acquire(unsigned* p) {
    unsigned v;
    asm volatile("ld.acquire.gpu.global.u32 %0, [%1];" : "=r"(v) : "l"(p) : "memory");
    return v;
}

__device__ __forceinline__ float hc_gate(float x) {
    float s = 1.0f / (1.0f + expf(-x));
    float v = s * 1.2f - 0.1f;
    return fminf(fmaxf(v, 0.0f), 1.0f);
}

// ---------------------------------------------------------------------------
// Phase 1: gate Wih + bias, zero h0, reset barrier counters
// ---------------------------------------------------------------------------
__global__ void regrnn_prep(const float* __restrict__ w_ih, const float* __restrict__ w_ih_mask,
                            const float* __restrict__ b_ih, const float* __restrict__ b_ih_mask,
                            const float* __restrict__ b_hh, const float* __restrict__ b_hh_mask) {
    int i = blockIdx.x * blockDim.x + threadIdx.x;
    if (i < Hh * Ii) {
        g_Wih[i] = hc_gate(w_ih_mask[i]) * w_ih[i];
    }
    if (i < Hh) {
        g_bias[i] = hc_gate(b_ih_mask[i]) * b_ih[i] + hc_gate(b_hh_mask[i]) * b_hh[i];
    }
    if (i < 2 * Hh * Bb) g_hT[i] = 0.0f;
    if (i < 256) g_cnt[i] = 0u;
    if (i < 32) g_done[i] = 0u;
}

// launch-phase shifter: 4 launches/call -> ncu capture index 3 = rnn
__global__ void regrnn_dummy1() { if (threadIdx.x == 1024) g_dummy = 1u; }

// ---------------------------------------------------------------------------
// Phase 2: x_proj GEMM. 128x128 tile, 8m x 8n micro, software-pipelined.
// Warp shape rebalanced: 8 m-octets x 4 n-octets per warp ->
// unique LDS/warp/k = 384B (was 576B), relieving the smem crossbar.
// ---------------------------------------------------------------------------
__global__ void __launch_bounds__(256, 2) regrnn_xproj(const float* __restrict__ A,
                                                       float* __restrict__ out) {
    __shared__ __align__(16) float As[16][132];
    __shared__ __align__(16) float Bs[16][132];
    const int m0 = blockIdx.y * 128;
    const int n0 = blockIdx.x * 128;
    const int t = threadIdx.x;
    const int wid = t >> 5;
    const int lane = t & 31;
    const int ty = ((wid & 1) << 3) + (lane >> 2);   // m-octet 0..15 (8 per warp)
    const int tx = ((wid >> 1) << 2) + (lane & 3);   // n-octet 0..15 (4 per warp)

    u64t acc[8][4];
#pragma unroll
    for (int i = 0; i < 8; i++)
#pragma unroll
        for (int j = 0; j < 4; j++) acc[i][j] = 0ULL;

    const int mS0 = t >> 2;            // 0..63
    const int kS0 = (t & 3) << 2;
    const int mS1 = mS0 + 64;          // 64..127

    const float* pA0 = A + (size_t)(m0 + mS0) * Ii + kS0;
    const float* pA1 = A + (size_t)(m0 + mS1) * Ii + kS0;
    const float* pB0 = g_Wih + (size_t)(n0 + mS0) * Ii + kS0;
    const float* pB1 = g_Wih + (size_t)(n0 + mS1) * Ii + kS0;

    // prefetch tile 0
    float4 a0v = *(const float4*)(pA0);
    float4 a1v = *(const float4*)(pA1);
    float4 b0v = *(const float4*)(pB0);
    float4 b1v = *(const float4*)(pB1);

    for (int kt = 0; kt < Ii; kt += 16) {
        As[kS0 + 0][mS0] = a0v.x; As[kS0 + 1][mS0] = a0v.y;
        As[kS0 + 2][mS0] = a0v.z; As[kS0 + 3][mS0] = a0v.w;
        As[kS0 + 0][mS1] = a1v.x; As[kS0 + 1][mS1] = a1v.y;
        As[kS0 + 2][mS1] = a1v.z; As[kS0 + 3][mS1] = a1v.w;
        Bs[kS0 + 0][mS0] = b0v.x; Bs[kS0 + 1][mS0] = b0v.y;
        Bs[kS0 + 2][mS0] = b0v.z; Bs[kS0 + 3][mS0] = b0v.w;
        Bs[kS0 + 0][mS1] = b1v.x; Bs[kS0 + 1][mS1] = b1v.y;
        Bs[kS0 + 2][mS1] = b1v.z; Bs[kS0 + 3][mS1] = b1v.w;
        __syncthreads();

        if (kt + 16 < Ii) {
            a0v = *(const float4*)(pA0 + kt + 16);
            a1v = *(const float4*)(pA1 + kt + 16);
            b0v = *(const float4*)(pB0 + kt + 16);
            b1v = *(const float4*)(pB1 + kt + 16);
        }

#pragma unroll
        for (int kk = 0; kk < 16; kk++) {
            float4 a0 = *(const float4*)&As[kk][ty << 3];
            float4 a1 = *(const float4*)&As[kk][(ty << 3) + 4];
            ulonglong2 b01 = *(const ulonglong2*)&Bs[kk][tx << 3];
            ulonglong2 b23 = *(const ulonglong2*)&Bs[kk][(tx << 3) + 4];
            float am[8] = {a0.x, a0.y, a0.z, a0.w, a1.x, a1.y, a1.z, a1.w};
#pragma unroll
            for (int mi = 0; mi < 8; mi++) {
                u64t s = pack2(am[mi], am[mi]);
                acc[mi][0] = fma2(s, b01.x, acc[mi][0]);
                acc[mi][1] = fma2(s, b01.y, acc[mi][1]);
                acc[mi][2] = fma2(s, b23.x, acc[mi][2]);
                acc[mi][3] = fma2(s, b23.y, acc[mi][3]);
            }
        }
        __syncthreads();
    }

    const int n = n0 + (tx << 3);
    ulonglong2 bv0 = *(const ulonglong2*)(g_bias + n);
    ulonglong2 bv1 = *(const ulonglong2*)(g_bias + n + 4);
#pragma unroll
    for (int i = 0; i < 8; i++) {
        int m = m0 + (ty << 3) + i;
        ulonglong2 st0, st1;
        st0.x = add2(acc[i][0], bv0.x); st0.y = add2(acc[i][1], bv0.y);
        st1.x = add2(acc[i][2], bv1.x); st1.y = add2(acc[i][3], bv1.y);
        *(ulonglong2*)(out + (size_t)m * Hh + n) = st0;
        *(ulonglong2*)(out + (size_t)m * Hh + n + 4) = st1;
    }
}

// ---------------------------------------------------------------------------
// Phase 3: persistent recurrence with TWO interleaved batch-group chains.
// 128 CTAs = 32 col-groups x 4 pair-slots. CTA owns 32 cols and batch groups
// gA = pr (batches pr*8..+8) and gB = pr+4 (batches 32+pr*8..+8).
// 8 independent 32-CTA barrier domains; each group's barrier latency hides
// behind the other group's compute.
// 8 warps = K-split (128 k, rotated). Thread micro: 4 cols x 2 batches.
// ---------------------------------------------------------------------------
struct RnnCtx {
    float* Wsh; float* hw; uint32_t hw_u32; float* red;
    int t, lane, w, cp8, bp, kbase;
    int c_l, b_l, c_g, rflat;
};

__device__ __forceinline__ void rnn_substep(
    const RnnCtx& cx, int step, int B0, unsigned* cnt, float* outp)
{
    const float* hsrc = g_hT + (step & 1) * (Hh * Bb);
    float* hdst = g_hT + ((step & 1) ^ 1) * (Hh * Bb);

    // wait for this group's step-s inputs (released one full other-group
    // substep ago -> usually fast-path)
    if (cx.t == 0) {
        unsigned target = 32u * (unsigned)step;
        while (ld_acquire(cnt) < target) { }
    }
    __syncthreads();

    // stage 4 rounds of 32k x 8b (64 chunks/round, 2 per lane)
#pragma unroll
    for (int r = 0; r < 4; r++) {
#pragma unroll
        for (int i = 0; i < 2; i++) {
            int id = cx.lane + (i << 5);       // 0..63
            int kk = id >> 1;                  // 0..31
            int b4 = (id & 1) << 2;
            cpasync16(cx.hw_u32 + ((r * 256 + kk * 8 + b4) << 2),
                      hsrc + (cx.kbase + r * 32 + kk) * Bb + B0 + b4);
        }
        CP_COMMIT();
    }

    // x_proj value for this thread's output
    const int xi = ((B0 + cx.b_l) * Tt + step) * Hh + cx.c_g;
    float xp = __ldcs(outp + xi);

    u64t acc[4] = {0ULL, 0ULL, 0ULL, 0ULL};

#pragma unroll
    for (int r = 0; r < 4; r++) {
        switch (r) {
            case 0: asm volatile("cp.async.wait_group 3;"); break;
            case 1: asm volatile("cp.async.wait_group 2;"); break;
            case 2: asm volatile("cp.async.wait_group 1;"); break;
            default: asm volatile("cp.async.wait_group 0;"); break;
        }
        __syncwarp();
        const float* hb = cx.hw + r * 256;
        const int kr = cx.kbase + r * 32;
#pragma unroll
        for (int kk = 0; kk < 32; kk++) {
            float4 w4 = *(const float4*)&cx.Wsh[(kr + kk) * 32 + (cx.cp8 << 2)];
            u64t h2 = *(const u64t*)&hb[kk * 8 + (cx.bp << 1)];
            acc[0] = fma2(pack2(w4.x, w4.x), h2, acc[0]);
            acc[1] = fma2(pack2(w4.y, w4.y), h2, acc[1]);
            acc[2] = fma2(pack2(w4.z, w4.z), h2, acc[2]);
            acc[3] = fma2(pack2(w4.w, w4.w), h2, acc[3]);
        }
    }

    // partials: red[w][cp8*32 + bp*8 + ci*2 + b01] (contiguous 8 fl/thread)
    {
        float* rw = cx.red + cx.w * 256 + (cx.cp8 << 5) + (cx.bp << 3);
        ulonglong2 v0; v0.x = acc[0]; v0.y = acc[1];
        ulonglong2 v1; v1.x = acc[2]; v1.y = acc[3];
        *(ulonglong2*)&rw[0] = v0;
        *(ulonglong2*)&rw[4] = v1;
    }
    __syncthreads();

    // reduce 8 partials, tanh
    float s = 0.0f;
#pragma unroll
    for (int ww = 0; ww < 8; ww++) s += cx.red[ww * 256 + cx.rflat];
    float hv = tanhf(xp + s);
    if (step < Tt - 1) __stcg(hdst + cx.c_g * Bb + B0 + cx.b_l, hv);

    __syncthreads();   // h stores HB-before t0's release; also guards red reuse
    if (cx.t == 0 && step < Tt - 1) arrive_release(cnt);

    // out writes off the critical path
    __stcs(outp + xi, hv);
    if (step == Tt - 1) {
        outp[Bb * Tt * Hh + (B0 + cx.b_l) * Hh + cx.c_g] = hv;
    }
}

__global__ void __launch_bounds__(256, 1) regrnn_rnn(
    const float* __restrict__ w_hh, const float* __restrict__ w_hh_mask,
    float* __restrict__ out)
{
    extern __shared__ __align__(16) float sm[];
    float* Wsh = sm;                    // [1024][32]
    float* hsAll = sm + 32768;          // [8 warps][4 rounds][32 k][8 b]
    float* red = sm + 32768 + 8192;     // [8][256]

    const int t = threadIdx.x;
    const int w = t >> 5;
    const int lane = t & 31;
    const int cg = blockIdx.x >> 2;     // col group 0..31
    const int pr = blockIdx.x & 3;      // pair slot 0..3
    const int C0 = cg * 32;
    const int B0a = pr * 8;             // group gA = pr
    const int B0b = 32 + pr * 8;        // group gB = pr + 4

    // gate + transpose W slice into smem: Wsh[k*32 + c]
    for (int i = t; i < 8192; i += 256) {
        int c = i & 31;
        int k4 = (i >> 5) << 2;
        size_t base = (size_t)(C0 + c) * Ii + k4;
        float4 wv = *(const float4*)(w_hh + base);
        float4 mv = *(const float4*)(w_hh_mask + base);
        Wsh[(k4 + 0) * 32 + c] = hc_gate(mv.x) * wv.x;
        Wsh[(k4 + 1) * 32 + c] = hc_gate(mv.y) * wv.y;
        Wsh[(k4 + 2) * 32 + c] = hc_gate(mv.z) * wv.z;
        Wsh[(k4 + 3) * 32 + c] = hc_gate(mv.w) * wv.w;
    }

    RnnCtx cx;
    cx.Wsh = Wsh;
    cx.red = red;
    cx.t = t; cx.lane = lane; cx.w = w;
    cx.cp8 = lane >> 2;                 // col-quad 0..7
    cx.bp = lane & 3;                   // batch-pair 0..3
    cx.hw = hsAll + w * 1024;           // 4 round-buffers x 256 fl
    cx.hw_u32 = (uint32_t)__cvta_generic_to_shared(cx.hw);
    cx.kbase = ((w + cg) & 7) * 128;
    cx.c_l = t >> 3;                    // 0..31
    cx.b_l = t & 7;                     // 0..7
    cx.c_g = C0 + cx.c_l;
    cx.rflat = ((cx.c_l >> 2) << 5) + ((cx.b_l >> 1) << 3)
             + ((cx.c_l & 3) << 1) + (cx.b_l & 1);

    unsigned* cntA = &g_cnt[pr * 32];
    unsigned* cntB = &g_cnt[(pr + 4) * 32];

    __syncthreads();

    for (int step = 0; step < Tt; step++) {
        rnn_substep(cx, step, B0a, cntA, out);
        rnn_substep(cx, step, B0b, cntB, out);
    }

    // exit protocol: reset counters for next graph replay
    if (t == 0) {
        arrive_release(&g_done[0]);
        if (blockIdx.x == 0) {
            while (ld_acquire(&g_done[0]) < 128u) { }
#pragma unroll 8
            for (int i = 0; i < 256; i++) g_cnt[i] = 0u;
            g_done[0] = 0u;
        }
    }
}

// ---------------------------------------------------------------------------
extern "C" void kernel_launch(void* const* d_in, const int* in_sizes, int n_in,
                              void* d_out, int out_size) {
    (void)in_sizes; (void)n_in; (void)out_size;
    const float* seq       = (const float*)d_in[0];
    const float* w_ih      = (const float*)d_in[1];
    const float* w_ih_mask = (const float*)d_in[2];
    const float* w_hh      = (const float*)d_in[3];
    const float* w_hh_mask = (const float*)d_in[4];
    const float* b_ih      = (const float*)d_in[5];
    const float* b_ih_mask = (const float*)d_in[6];
    const float* b_hh      = (const float*)d_in[7];
    const float* b_hh_mask = (const float*)d_in[8];
    float* out = (float*)d_out;

    regrnn_prep<<<(Hh * Ii + 255) / 256, 256>>>(w_ih, w_ih_mask,
                                                b_ih, b_ih_mask, b_hh, b_hh_mask);
    regrnn_dummy1<<<1, 32>>>();
    regrnn_xproj<<<dim3(Hh / 128, (Bb * Tt) / 128), 256>>>(seq, out);

    cudaFuncSetAttribute(regrnn_rnn, cudaFuncAttributeMaxDynamicSharedMemorySize, RNN_SMEM_BYTES);
    regrnn_rnn<<<RNN_CTAS, 256, RNN_SMEM_BYTES>>>(w_hh, w_hh_mask, out);
}

// round 12
// speedup vs baseline: 1.4101x; 1.4101x over previous
#include <cuda_runtime.h>
#include <cuda_bf16.h>
#include <cstdint>

#define Bb 64
#define Tt 512
#define Ii 1024
#define Hh 1024

#define FUSED_CTAS 128
#define TOTAL_CTAS 148
#define XP_UNITS 168          // 128 fused halves + 20*2 pure halves
#define XP_TILES 2048         // 16 blk * (16 bq * 8 nb)
#define XP_BLKS 16
#define XP_TILES_PER_BLK 128

// smem floats: rnn (Wsh 32768 + hs 16384 + red 4096) + xproj role-B (2*2112)
#define RNN_FLOATS (32768 + 16384 + 4096)
#define XP_ROLE_FLOATS (2 * 16 * 132)
#define SMEM_BYTES ((RNN_FLOATS + XP_ROLE_FLOATS) * 4)   // 229,888 B

__device__ __align__(16) float g_Wih[Hh * Ii];
__device__ __align__(16) float g_bias[Hh];
__device__ __align__(16) float g_hT[2 * Hh * Bb];   // double-buffered h, [k][b]
__device__ unsigned g_cnt[128];     // 4 h-barrier domains, stride 32
__device__ unsigned g_xcnt[XP_BLKS];// xproj per-t-block completion counters
__device__ unsigned g_done;

typedef unsigned long long u64t;

__device__ __forceinline__ u64t pack2(float x, float y) {
    u64t r; asm("mov.b64 %0, {%1,%2};" : "=l"(r) : "f"(x), "f"(y)); return r;
}
__device__ __forceinline__ u64t fma2(u64t a, u64t b, u64t c) {
    u64t d; asm("fma.rn.f32x2 %0, %1, %2, %3;" : "=l"(d) : "l"(a), "l"(b), "l"(c)); return d;
}
__device__ __forceinline__ u64t add2(u64t a, u64t b) {
    u64t d; asm("add.rn.f32x2 %0, %1, %2;" : "=l"(d) : "l"(a), "l"(b)); return d;
}
__device__ __forceinline__ void cpasync16(uint32_t dst, const void* src) {
    asm volatile("cp.async.cg.shared.global [%0], [%1], 16;" :: "r"(dst), "l"(src));
}
#define CP_COMMIT() asm volatile("cp.async.commit_group;")
#define BARX(id) asm volatile("bar.sync %0, %1;" :: "r"(id), "r"(256) : "memory")

__device__ __forceinline__ void arrive_release(unsigned* p) {
    asm volatile("red.release.gpu.global.add.u32 [%0], %1;" :: "l"(p), "r"(1u) : "memory");
}
__device__ __forceinline__ unsigned ld_acquire(unsigned* p) {
    unsigned v;
    asm volatile("ld.acquire.gpu.global.u32 %0, [%1];" : "=r"(v) : "l"(p) : "memory");
    return v;
}

__device__ __forceinline__ float hc_gate(float x) {
    float s = 1.0f / (1.0f + expf(-x));
    float v = s * 1.2f - 0.1f;
    return fminf(fmaxf(v, 0.0f), 1.0f);
}

// ---------------------------------------------------------------------------
// Phase 1: gate Wih + bias, zero h0, reset counters
// ---------------------------------------------------------------------------
__global__ void regrnn_prep(const float* __restrict__ w_ih, const float* __restrict__ w_ih_mask,
                            const float* __restrict__ b_ih, const float* __restrict__ b_ih_mask,
                            const float* __restrict__ b_hh, const float* __restrict__ b_hh_mask) {
    int i = blockIdx.x * blockDim.x + threadIdx.x;
    if (i < Hh * Ii) {
        g_Wih[i] = hc_gate(w_ih_mask[i]) * w_ih[i];
    }
    if (i < Hh) {
        g_bias[i] = hc_gate(b_ih_mask[i]) * b_ih[i] + hc_gate(b_hh_mask[i]) * b_hh[i];
    }
    if (i < 2 * Hh * Bb) g_hT[i] = 0.0f;
    if (i < 128) g_cnt[i] = 0u;
    if (i < XP_BLKS) g_xcnt[i] = 0u;
    if (i == 0) g_done = 0u;
}

// ---------------------------------------------------------------------------
// xproj role: one 256-thread half processes tiles unit, unit+168, ...
// Tile = (4 batches x 32 timesteps) x 128 n, t-block-major order.
// Publishes g_xcnt[blk] after each tile.
// ---------------------------------------------------------------------------
__device__ void xproj_role(int rtid, int bid, float* As, float* Bs, int unit,
                           const float* __restrict__ A, float* __restrict__ out)
{
    const int wrole = rtid >> 5;
    const int lane = rtid & 31;
    // rebalanced warp shape: 8 m-octets x 4 n-octets per warp
    const int ty = ((wrole & 1) << 3) + (lane >> 2);   // m-octet 0..15
    const int tx = ((wrole >> 1) << 2) + (lane & 3);   // n-octet 0..15

    const int i0 = rtid >> 2;            // staging row 0..63
    const int k4 = (rtid & 3) << 2;
    const int i1 = i0 + 64;

    for (int tau = unit; tau < XP_TILES; tau += XP_UNITS) {
        const int blk = tau >> 7;
        const int r = tau & 127;
        const int b0 = (r >> 3) << 2;       // 4-batch group
        const int n0 = (r & 7) << 7;        // n-tile
        const int t0 = blk << 5;            // 32-t block

        const int mrow0 = (b0 + (i0 >> 5)) * Tt + t0 + (i0 & 31);
        const int mrow1 = (b0 + (i1 >> 5)) * Tt + t0 + (i1 & 31);
        const float* pA0 = A + (size_t)mrow0 * Ii + k4;
        const float* pA1 = A + (size_t)mrow1 * Ii + k4;
        const float* pB0 = g_Wih + (size_t)(n0 + i0) * Ii + k4;
        const float* pB1 = g_Wih + (size_t)(n0 + i1) * Ii + k4;

        u64t acc[8][4];
#pragma unroll
        for (int i = 0; i < 8; i++)
#pragma unroll
            for (int j = 0; j < 4; j++) acc[i][j] = 0ULL;

        float4 a0v = *(const float4*)(pA0);
        float4 a1v = *(const float4*)(pA1);
        float4 b0v = *(const float4*)(pB0);
        float4 b1v = *(const float4*)(pB1);

        for (int kt = 0; kt < Ii; kt += 16) {
            As[(k4 + 0) * 132 + i0] = a0v.x; As[(k4 + 1) * 132 + i0] = a0v.y;
            As[(k4 + 2) * 132 + i0] = a0v.z; As[(k4 + 3) * 132 + i0] = a0v.w;
            As[(k4 + 0) * 132 + i1] = a1v.x; As[(k4 + 1) * 132 + i1] = a1v.y;
            As[(k4 + 2) * 132 + i1] = a1v.z; As[(k4 + 3) * 132 + i1] = a1v.w;
            Bs[(k4 + 0) * 132 + i0] = b0v.x; Bs[(k4 + 1) * 132 + i0] = b0v.y;
            Bs[(k4 + 2) * 132 + i0] = b0v.z; Bs[(k4 + 3) * 132 + i0] = b0v.w;
            Bs[(k4 + 0) * 132 + i1] = b1v.x; Bs[(k4 + 1) * 132 + i1] = b1v.y;
            Bs[(k4 + 2) * 132 + i1] = b1v.z; Bs[(k4 + 3) * 132 + i1] = b1v.w;
            BARX(bid);

            if (kt + 16 < Ii) {
                a0v = *(const float4*)(pA0 + kt + 16);
                a1v = *(const float4*)(pA1 + kt + 16);
                b0v = *(const float4*)(pB0 + kt + 16);
                b1v = *(const float4*)(pB1 + kt + 16);
            }

#pragma unroll
            for (int kk = 0; kk < 16; kk++) {
                float4 a0 = *(const float4*)&As[kk * 132 + (ty << 3)];
                float4 a1 = *(const float4*)&As[kk * 132 + (ty << 3) + 4];
                ulonglong2 b01 = *(const ulonglong2*)&Bs[kk * 132 + (tx << 3)];
                ulonglong2 b23 = *(const ulonglong2*)&Bs[kk * 132 + (tx << 3) + 4];
                float am[8] = {a0.x, a0.y, a0.z, a0.w, a1.x, a1.y, a1.z, a1.w};
#pragma unroll
                for (int mi = 0; mi < 8; mi++) {
                    u64t s = pack2(am[mi], am[mi]);
                    acc[mi][0] = fma2(s, b01.x, acc[mi][0]);
                    acc[mi][1] = fma2(s, b01.y, acc[mi][1]);
                    acc[mi][2] = fma2(s, b23.x, acc[mi][2]);
                    acc[mi][3] = fma2(s, b23.y, acc[mi][3]);
                }
            }
            BARX(bid);
        }

        const int n = n0 + (tx << 3);
        ulonglong2 bv0 = *(const ulonglong2*)(g_bias + n);
        ulonglong2 bv1 = *(const ulonglong2*)(g_bias + n + 4);
#pragma unroll
        for (int i = 0; i < 8; i++) {
            int mi = (ty << 3) + i;
            int mrow = (b0 + (mi >> 5)) * Tt + t0 + (mi & 31);
            ulonglong2 st0, st1;
            st0.x = add2(acc[i][0], bv0.x); st0.y = add2(acc[i][1], bv0.y);
            st1.x = add2(acc[i][2], bv1.x); st1.y = add2(acc[i][3], bv1.y);
            *(ulonglong2*)(out + (size_t)mrow * Hh + n) = st0;
            *(ulonglong2*)(out + (size_t)mrow * Hh + n + 4) = st1;
        }
        BARX(bid);   // all stores done before counting
        if (rtid == 0) arrive_release(&g_xcnt[blk]);
    }
}

// ---------------------------------------------------------------------------
// rnn role: R10 recurrence (8 warps, K-split, quad-buffered cp.async,
// single-counter barrier), with named barrier id 1 and xcnt gating.
// ---------------------------------------------------------------------------
__device__ void rnn_role(int t, int cta,
                         const float* __restrict__ w_hh, const float* __restrict__ w_hh_mask,
                         float* __restrict__ out, float* sm)
{
    float* Wsh = sm;                    // [1024][32]
    float* hsAll = sm + 32768;          // [8 warps][4 rounds][32 k][16 b]
    float* red = sm + 32768 + 16384;    // [8][512]

    const int w = t >> 5;
    const int lane = t & 31;
    const int cg = cta >> 2;            // col group 0..31
    const int bg = cta & 3;             // batch group 0..3
    const int C0 = cg * 32;
    const int B0 = bg * 16;

    for (int i = t; i < 8192; i += 256) {
        int c = i & 31;
        int k4 = (i >> 5) << 2;
        size_t base = (size_t)(C0 + c) * Ii + k4;
        float4 wv = *(const float4*)(w_hh + base);
        float4 mv = *(const float4*)(w_hh_mask + base);
        Wsh[(k4 + 0) * 32 + c] = hc_gate(mv.x) * wv.x;
        Wsh[(k4 + 1) * 32 + c] = hc_gate(mv.y) * wv.y;
        Wsh[(k4 + 2) * 32 + c] = hc_gate(mv.z) * wv.z;
        Wsh[(k4 + 3) * 32 + c] = hc_gate(mv.w) * wv.w;
    }

    const int cp8 = lane >> 2;
    const int bq = lane & 3;
    float* hw = hsAll + w * 2048;
    uint32_t hw_u32 = (uint32_t)__cvta_generic_to_shared(hw);
    const int kbase = ((w + cg) & 7) * 128;

    const int o0 = 2 * t;
    const int c_l = o0 >> 4;
    const int b_l = o0 & 15;
    const int c_g = C0 + c_l;
    const int rflat = (c_l >> 2) * 64 + (b_l >> 2) * 16 + (c_l & 3) * 4 + (b_l & 3);

    unsigned* cnt = &g_cnt[bg * 32];

    int xi0 = ((B0 + b_l) * Tt) * Hh + c_g;
    int xi1 = ((B0 + b_l + 1) * Tt) * Hh + c_g;

    // gate x_proj block 0 before first step
    if (t == 0) {
        while (ld_acquire(&g_xcnt[0]) < XP_TILES_PER_BLK) { }
    }
    BARX(1);

    for (int step = 0; step < Tt; step++) {
        const float* hsrc = g_hT + (step & 1) * (Hh * Bb);
        float* hdst = g_hT + ((step & 1) ^ 1) * (Hh * Bb);

        // stage ALL 4 rounds (quad-buffered)
#pragma unroll
        for (int r = 0; r < 4; r++) {
#pragma unroll
            for (int i = 0; i < 4; i++) {
                int fid = lane + (i << 5);
                int kk = fid >> 2;
                int c4 = (fid & 3) << 2;
                cpasync16(hw_u32 + ((r * 512 + kk * 16 + c4) << 2),
                          hsrc + (kbase + r * 32 + kk) * Bb + B0 + c4);
            }
            CP_COMMIT();
        }

        // x_proj values (gated by xcnt for this step's block)
        float xp0 = __ldcg(out + xi0);
        float xp1 = __ldcg(out + xi1);

        u64t acc[4][2];
#pragma unroll
        for (int i = 0; i < 4; i++) { acc[i][0] = 0ULL; acc[i][1] = 0ULL; }

#pragma unroll
        for (int r = 0; r < 4; r++) {
            switch (r) {
                case 0: asm volatile("cp.async.wait_group 3;"); break;
                case 1: asm volatile("cp.async.wait_group 2;"); break;
                case 2: asm volatile("cp.async.wait_group 1;"); break;
                default: asm volatile("cp.async.wait_group 0;"); break;
            }
            __syncwarp();
            const float* hb = hw + r * 512;
            const int kr = kbase + r * 32;
#pragma unroll
            for (int kk = 0; kk < 32; kk++) {
                float4 w4 = *(const float4*)&Wsh[(kr + kk) * 32 + (cp8 << 2)];
                ulonglong2 h2 = *(const ulonglong2*)&hb[kk * 16 + (bq << 2)];
                u64t s0 = pack2(w4.x, w4.x);
                u64t s1 = pack2(w4.y, w4.y);
                u64t s2 = pack2(w4.z, w4.z);
                u64t s3 = pack2(w4.w, w4.w);
                acc[0][0] = fma2(s0, h2.x, acc[0][0]); acc[0][1] = fma2(s0, h2.y, acc[0][1]);
                acc[1][0] = fma2(s1, h2.x, acc[1][0]); acc[1][1] = fma2(s1, h2.y, acc[1][1]);
                acc[2][0] = fma2(s2, h2.x, acc[2][0]); acc[2][1] = fma2(s2, h2.y, acc[2][1]);
                acc[3][0] = fma2(s3, h2.x, acc[3][0]); acc[3][1] = fma2(s3, h2.y, acc[3][1]);
            }
        }

        {
            float* rw = red + w * 512 + (cp8 << 6) + (bq << 4);
#pragma unroll
            for (int ci = 0; ci < 4; ci++) {
                ulonglong2 v; v.x = acc[ci][0]; v.y = acc[ci][1];
                *(ulonglong2*)&rw[ci << 2] = v;
            }
        }
        BARX(1);

        float sx = 0.0f, sy = 0.0f;
#pragma unroll
        for (int ww = 0; ww < 8; ww++) {
            float2 v = *(const float2*)&red[ww * 512 + rflat];
            sx += v.x; sy += v.y;
        }
        float hv0 = tanhf(xp0 + sx);
        float hv1 = tanhf(xp1 + sy);
        __stcg((float2*)(hdst + c_g * Bb + B0 + b_l), make_float2(hv0, hv1));

        BARX(1);   // h stores HB-before t0's release
        if (t == 0 && step < Tt - 1) {
            arrive_release(cnt);
            unsigned target = 32u * (unsigned)(step + 1);
            while (ld_acquire(cnt) < target) { }
            int nb = (step + 1) >> 5;
            while (ld_acquire(&g_xcnt[nb]) < XP_TILES_PER_BLK) { }
        }
        // out writes overlap t0's spin
        __stcg(out + xi0, hv0);
        __stcg(out + xi1, hv1);
        if (step == Tt - 1) {
            out[Bb * Tt * Hh + (B0 + b_l) * Hh + c_g] = hv0;
            out[Bb * Tt * Hh + (B0 + b_l + 1) * Hh + c_g] = hv1;
        }
        xi0 += Hh; xi1 += Hh;
        BARX(1);
    }
}

// ---------------------------------------------------------------------------
// Fused persistent kernel.
// CTAs 0..127: warps 0-7 rnn, warps 8-15 xproj (unit = cta).
// CTAs 128..147: both halves xproj (units 128 + (cta-128)*2 + half).
// ---------------------------------------------------------------------------
__global__ void __launch_bounds__(512, 1) regrnn_fused(
    const float* __restrict__ seq,
    const float* __restrict__ w_hh, const float* __restrict__ w_hh_mask,
    float* __restrict__ out)
{
    extern __shared__ __align__(16) float sm[];
    const int t = threadIdx.x;
    const int cta = blockIdx.x;
    const int half = t >> 8;            // 0: warps 0-7, 1: warps 8-15
    const int rtid = t & 255;

    float* xpB_As = sm + RNN_FLOATS;            // role-B xproj buffers
    float* xpB_Bs = xpB_As + 16 * 132;
    float* xpA_As = sm;                          // role-A (pure CTAs only)
    float* xpA_Bs = xpA_As + 16 * 132;

    if (cta < FUSED_CTAS) {
        if (half == 0) {
            rnn_role(rtid, cta, w_hh, w_hh_mask, out, sm);
        } else {
            xproj_role(rtid, 2, xpB_As, xpB_Bs, cta, seq, out);
        }
    } else {
        if (half == 0) {
            xproj_role(rtid, 1, xpA_As, xpA_Bs, FUSED_CTAS + (cta - FUSED_CTAS) * 2, seq, out);
        } else {
            xproj_role(rtid, 2, xpB_As, xpB_Bs, FUSED_CTAS + (cta - FUSED_CTAS) * 2 + 1, seq, out);
        }
    }

    // exit protocol: last CTA resets all counters for next graph replay
    if (t == 0) {
        __threadfence();
        unsigned old = atomicAdd(&g_done, 1u);
        if (old == TOTAL_CTAS - 1) {
#pragma unroll 8
            for (int i = 0; i < 128; i++) g_cnt[i] = 0u;
#pragma unroll
            for (int i = 0; i < XP_BLKS; i++) g_xcnt[i] = 0u;
            __threadfence();
            g_done = 0u;
        }
    }
}

// ---------------------------------------------------------------------------
extern "C" void kernel_launch(void* const* d_in, const int* in_sizes, int n_in,
                              void* d_out, int out_size) {
    (void)in_sizes; (void)n_in; (void)out_size;
    const float* seq       = (const float*)d_in[0];
    const float* w_ih      = (const float*)d_in[1];
    const float* w_ih_mask = (const float*)d_in[2];
    const float* w_hh      = (const float*)d_in[3];
    const float* w_hh_mask = (const float*)d_in[4];
    const float* b_ih      = (const float*)d_in[5];
    const float* b_ih_mask = (const float*)d_in[6];
    const float* b_hh      = (const float*)d_in[7];
    const float* b_hh_mask = (const float*)d_in[8];
    float* out = (float*)d_out;

    regrnn_prep<<<(Hh * Ii + 255) / 256, 256>>>(w_ih, w_ih_mask,
                                                b_ih, b_ih_mask, b_hh, b_hh_mask);

    cudaFuncSetAttribute(regrnn_fused, cudaFuncAttributeMaxDynamicSharedMemorySize, SMEM_BYTES);
    regrnn_fused<<<TOTAL_CTAS, 512, SMEM_BYTES>>>(seq, w_hh, w_hh_mask, out);
}

// round 13
// speedup vs baseline: 1.5168x; 1.0757x over previous
#include <cuda_runtime.h>
#include <cuda_bf16.h>
#include <cstdint>

#define Bb 64
#define Tt 512
#define Ii 1024
#define Hh 1024

#define FUSED_CTAS 128
#define TOTAL_CTAS 148
#define XP_UNITS 168          // 128 fused halves + 20*2 pure halves
#define XP_TILES 2048         // 16 blk * (16 bq * 8 nb)
#define XP_BLKS 16
#define XP_TILES_PER_BLK 128

// smem floats: rnn (Wsh 32768 + hs 16384 + red 8*576=4608) + xproj role-B (2*2112)
#define RNN_FLOATS (32768 + 16384 + 4608)
#define XP_ROLE_FLOATS (2 * 16 * 132)
#define SMEM_BYTES ((RNN_FLOATS + XP_ROLE_FLOATS) * 4)   // 231,936 B

__device__ __align__(16) float g_Wih[Hh * Ii];
__device__ __align__(16) float g_bias[Hh];
__device__ __align__(16) float g_hT[2 * Hh * Bb];   // double-buffered h, [k][b]
__device__ unsigned g_cnt[128];     // 4 h-barrier domains, stride 32
__device__ unsigned g_xcnt[XP_BLKS];// xproj per-t-block completion counters
__device__ unsigned g_done;

typedef unsigned long long u64t;

__device__ __forceinline__ u64t pack2(float x, float y) {
    u64t r; asm("mov.b64 %0, {%1,%2};" : "=l"(r) : "f"(x), "f"(y)); return r;
}
__device__ __forceinline__ u64t fma2(u64t a, u64t b, u64t c) {
    u64t d; asm("fma.rn.f32x2 %0, %1, %2, %3;" : "=l"(d) : "l"(a), "l"(b), "l"(c)); return d;
}
__device__ __forceinline__ u64t add2(u64t a, u64t b) {
    u64t d; asm("add.rn.f32x2 %0, %1, %2;" : "=l"(d) : "l"(a), "l"(b)); return d;
}
__device__ __forceinline__ void cpasync16(uint32_t dst, const void* src) {
    asm volatile("cp.async.cg.shared.global [%0], [%1], 16;" :: "r"(dst), "l"(src));
}
#define CP_COMMIT() asm volatile("cp.async.commit_group;")
#define BARX(id) asm volatile("bar.sync %0, %1;" :: "r"(id), "r"(256) : "memory")

__device__ __forceinline__ void arrive_release(unsigned* p) {
    asm volatile("red.release.gpu.global.add.u32 [%0], %1;" :: "l"(p), "r"(1u) : "memory");
}
__device__ __forceinline__ unsigned ld_acquire(unsigned* p) {
    unsigned v;
    asm volatile("ld.acquire.gpu.global.u32 %0, [%1];" : "=r"(v) : "l"(p) : "memory");
    return v;
}

__device__ __forceinline__ float hc_gate(float x) {
    float s = 1.0f / (1.0f + expf(-x));
    float v = s * 1.2f - 0.1f;
    return fminf(fmaxf(v, 0.0f), 1.0f);
}

// ---------------------------------------------------------------------------
// Phase 1: gate Wih + bias, zero h0, reset counters
// ---------------------------------------------------------------------------
__global__ void regrnn_prep(const float* __restrict__ w_ih, const float* __restrict__ w_ih_mask,
                            const float* __restrict__ b_ih, const float* __restrict__ b_ih_mask,
                            const float* __restrict__ b_hh, const float* __restrict__ b_hh_mask) {
    int i = blockIdx.x * blockDim.x + threadIdx.x;
    if (i < Hh * Ii) {
        g_Wih[i] = hc_gate(w_ih_mask[i]) * w_ih[i];
    }
    if (i < Hh) {
        g_bias[i] = hc_gate(b_ih_mask[i]) * b_ih[i] + hc_gate(b_hh_mask[i]) * b_hh[i];
    }
    if (i < 2 * Hh * Bb) g_hT[i] = 0.0f;
    if (i < 128) g_cnt[i] = 0u;
    if (i < XP_BLKS) g_xcnt[i] = 0u;
    if (i == 0) g_done = 0u;
}

// ---------------------------------------------------------------------------
// xproj role (unchanged from R12 winner): one 256-thread half processes tiles
// unit, unit+168, ... Tile = (4 batches x 32 timesteps) x 128 n.
// ---------------------------------------------------------------------------
__device__ void xproj_role(int rtid, int bid, float* As, float* Bs, int unit,
                           const float* __restrict__ A, float* __restrict__ out)
{
    const int wrole = rtid >> 5;
    const int lane = rtid & 31;
    const int ty = ((wrole & 1) << 3) + (lane >> 2);   // m-octet 0..15
    const int tx = ((wrole >> 1) << 2) + (lane & 3);   // n-octet 0..15

    const int i0 = rtid >> 2;
    const int k4 = (rtid & 3) << 2;
    const int i1 = i0 + 64;

    for (int tau = unit; tau < XP_TILES; tau += XP_UNITS) {
        const int blk = tau >> 7;
        const int r = tau & 127;
        const int b0 = (r >> 3) << 2;
        const int n0 = (r & 7) << 7;
        const int t0 = blk << 5;

        const int mrow0 = (b0 + (i0 >> 5)) * Tt + t0 + (i0 & 31);
        const int mrow1 = (b0 + (i1 >> 5)) * Tt + t0 + (i1 & 31);
        const float* pA0 = A + (size_t)mrow0 * Ii + k4;
        const float* pA1 = A + (size_t)mrow1 * Ii + k4;
        const float* pB0 = g_Wih + (size_t)(n0 + i0) * Ii + k4;
        const float* pB1 = g_Wih + (size_t)(n0 + i1) * Ii + k4;

        u64t acc[8][4];
#pragma unroll
        for (int i = 0; i < 8; i++)
#pragma unroll
            for (int j = 0; j < 4; j++) acc[i][j] = 0ULL;

        float4 a0v = *(const float4*)(pA0);
        float4 a1v = *(const float4*)(pA1);
        float4 b0v = *(const float4*)(pB0);
        float4 b1v = *(const float4*)(pB1);

        for (int kt = 0; kt < Ii; kt += 16) {
            As[(k4 + 0) * 132 + i0] = a0v.x; As[(k4 + 1) * 132 + i0] = a0v.y;
            As[(k4 + 2) * 132 + i0] = a0v.z; As[(k4 + 3) * 132 + i0] = a0v.w;
            As[(k4 + 0) * 132 + i1] = a1v.x; As[(k4 + 1) * 132 + i1] = a1v.y;
            As[(k4 + 2) * 132 + i1] = a1v.z; As[(k4 + 3) * 132 + i1] = a1v.w;
            Bs[(k4 + 0) * 132 + i0] = b0v.x; Bs[(k4 + 1) * 132 + i0] = b0v.y;
            Bs[(k4 + 2) * 132 + i0] = b0v.z; Bs[(k4 + 3) * 132 + i0] = b0v.w;
            Bs[(k4 + 0) * 132 + i1] = b1v.x; Bs[(k4 + 1) * 132 + i1] = b1v.y;
            Bs[(k4 + 2) * 132 + i1] = b1v.z; Bs[(k4 + 3) * 132 + i1] = b1v.w;
            BARX(bid);

            if (kt + 16 < Ii) {
                a0v = *(const float4*)(pA0 + kt + 16);
                a1v = *(const float4*)(pA1 + kt + 16);
                b0v = *(const float4*)(pB0 + kt + 16);
                b1v = *(const float4*)(pB1 + kt + 16);
            }

#pragma unroll
            for (int kk = 0; kk < 16; kk++) {
                float4 a0 = *(const float4*)&As[kk * 132 + (ty << 3)];
                float4 a1 = *(const float4*)&As[kk * 132 + (ty << 3) + 4];
                ulonglong2 b01 = *(const ulonglong2*)&Bs[kk * 132 + (tx << 3)];
                ulonglong2 b23 = *(const ulonglong2*)&Bs[kk * 132 + (tx << 3) + 4];
                float am[8] = {a0.x, a0.y, a0.z, a0.w, a1.x, a1.y, a1.z, a1.w};
#pragma unroll
                for (int mi = 0; mi < 8; mi++) {
                    u64t s = pack2(am[mi], am[mi]);
                    acc[mi][0] = fma2(s, b01.x, acc[mi][0]);
                    acc[mi][1] = fma2(s, b01.y, acc[mi][1]);
                    acc[mi][2] = fma2(s, b23.x, acc[mi][2]);
                    acc[mi][3] = fma2(s, b23.y, acc[mi][3]);
                }
            }
            BARX(bid);
        }

        const int n = n0 + (tx << 3);
        ulonglong2 bv0 = *(const ulonglong2*)(g_bias + n);
        ulonglong2 bv1 = *(const ulonglong2*)(g_bias + n + 4);
#pragma unroll
        for (int i = 0; i < 8; i++) {
            int mi = (ty << 3) + i;
            int mrow = (b0 + (mi >> 5)) * Tt + t0 + (mi & 31);
            ulonglong2 st0, st1;
            st0.x = add2(acc[i][0], bv0.x); st0.y = add2(acc[i][1], bv0.y);
            st1.x = add2(acc[i][2], bv1.x); st1.y = add2(acc[i][3], bv1.y);
            *(ulonglong2*)(out + (size_t)mrow * Hh + n) = st0;
            *(ulonglong2*)(out + (size_t)mrow * Hh + n + 4) = st1;
        }
        BARX(bid);
        if (rtid == 0) arrive_release(&g_xcnt[blk]);
    }
}

// ---------------------------------------------------------------------------
// rnn role: 8 warps, K-split 8 with INTRA-WARP 2-way k-split.
// Thread micro-tile 8c x 4b (3 B/fma2, was 4): lane = ksub*16 + (cq*4 + bq).
// ksub halves take even/odd kk; one shfl_xor(16) level combines them.
// Partials: red[w][b*36 + c] (padded rows -> <=2-way STS conflicts).
// ---------------------------------------------------------------------------
__device__ void rnn_role(int t, int cta,
                         const float* __restrict__ w_hh, const float* __restrict__ w_hh_mask,
                         float* __restrict__ out, float* sm)
{
    float* Wsh = sm;                    // [1024][32]
    float* hsAll = sm + 32768;          // [8 warps][4 rounds][32 k][16 b]
    float* red = sm + 32768 + 16384;    // [8][16 b][36]  (576 fl/warp)

    const int w = t >> 5;
    const int lane = t & 31;
    const int cg = cta >> 2;            // col group 0..31
    const int bg = cta & 3;             // batch group 0..3
    const int C0 = cg * 32;
    const int B0 = bg * 16;

    for (int i = t; i < 8192; i += 256) {
        int c = i & 31;
        int k4 = (i >> 5) << 2;
        size_t base = (size_t)(C0 + c) * Ii + k4;
        float4 wv = *(const float4*)(w_hh + base);
        float4 mv = *(const float4*)(w_hh_mask + base);
        Wsh[(k4 + 0) * 32 + c] = hc_gate(mv.x) * wv.x;
        Wsh[(k4 + 1) * 32 + c] = hc_gate(mv.y) * wv.y;
        Wsh[(k4 + 2) * 32 + c] = hc_gate(mv.z) * wv.z;
        Wsh[(k4 + 3) * 32 + c] = hc_gate(mv.w) * wv.w;
    }

    const int ksub = lane >> 4;         // 0/1: even/odd kk
    const int tile = lane & 15;
    const int cq = tile >> 2;           // col-octet 0..3 (8 c each)
    const int bq = tile & 3;            // batch-quad 0..3 (4 b each)

    float* hw = hsAll + w * 2048;
    uint32_t hw_u32 = (uint32_t)__cvta_generic_to_shared(hw);
    const int kbase = ((w + cg) & 7) * 128;

    // reduction/epilogue mapping: thread owns (c_l, b2) and (c_l, b2+1)
    const int c_l = t >> 3;             // 0..31
    const int b2 = (t & 7) << 1;        // 0..14 even
    const int c_g = C0 + c_l;

    unsigned* cnt = &g_cnt[bg * 32];

    int xi0 = ((B0 + b2) * Tt) * Hh + c_g;
    int xi1 = ((B0 + b2 + 1) * Tt) * Hh + c_g;

    // gate x_proj block 0 before first step
    if (t == 0) {
        while (ld_acquire(&g_xcnt[0]) < XP_TILES_PER_BLK) { }
    }
    BARX(1);

    for (int step = 0; step < Tt; step++) {
        const float* hsrc = g_hT + (step & 1) * (Hh * Bb);
        float* hdst = g_hT + ((step & 1) ^ 1) * (Hh * Bb);

        // stage ALL 4 rounds (quad-buffered)
#pragma unroll
        for (int r = 0; r < 4; r++) {
#pragma unroll
            for (int i = 0; i < 4; i++) {
                int fid = lane + (i << 5);
                int kk = fid >> 2;
                int c4 = (fid & 3) << 2;
                cpasync16(hw_u32 + ((r * 512 + kk * 16 + c4) << 2),
                          hsrc + (kbase + r * 32 + kk) * Bb + B0 + c4);
            }
            CP_COMMIT();
        }

        // x_proj values (gated by xcnt for this step's block)
        float xp0 = __ldcg(out + xi0);
        float xp1 = __ldcg(out + xi1);

        u64t acc[4][4];   // [c-pair within octet][b]
#pragma unroll
        for (int i = 0; i < 4; i++)
#pragma unroll
            for (int j = 0; j < 4; j++) acc[i][j] = 0ULL;

#pragma unroll
        for (int r = 0; r < 4; r++) {
            switch (r) {
                case 0: asm volatile("cp.async.wait_group 3;"); break;
                case 1: asm volatile("cp.async.wait_group 2;"); break;
                case 2: asm volatile("cp.async.wait_group 1;"); break;
                default: asm volatile("cp.async.wait_group 0;"); break;
            }
            __syncwarp();
            const float* hb = hw + r * 512;
            const int kr = kbase + r * 32;
#pragma unroll
            for (int i = 0; i < 16; i++) {
                int kk = (i << 1) + ksub;
                ulonglong2 wp01 = *(const ulonglong2*)&Wsh[(kr + kk) * 32 + (cq << 3)];
                ulonglong2 wp23 = *(const ulonglong2*)&Wsh[(kr + kk) * 32 + (cq << 3) + 4];
                float4 h4 = *(const float4*)&hb[kk * 16 + (bq << 2)];
                u64t h0 = pack2(h4.x, h4.x);
                u64t h1 = pack2(h4.y, h4.y);
                u64t h2 = pack2(h4.z, h4.z);
                u64t h3 = pack2(h4.w, h4.w);
                acc[0][0] = fma2(wp01.x, h0, acc[0][0]);
                acc[0][1] = fma2(wp01.x, h1, acc[0][1]);
                acc[0][2] = fma2(wp01.x, h2, acc[0][2]);
                acc[0][3] = fma2(wp01.x, h3, acc[0][3]);
                acc[1][0] = fma2(wp01.y, h0, acc[1][0]);
                acc[1][1] = fma2(wp01.y, h1, acc[1][1]);
                acc[1][2] = fma2(wp01.y, h2, acc[1][2]);
                acc[1][3] = fma2(wp01.y, h3, acc[1][3]);
                acc[2][0] = fma2(wp23.x, h0, acc[2][0]);
                acc[2][1] = fma2(wp23.x, h1, acc[2][1]);
                acc[2][2] = fma2(wp23.x, h2, acc[2][2]);
                acc[2][3] = fma2(wp23.x, h3, acc[2][3]);
                acc[3][0] = fma2(wp23.y, h0, acc[3][0]);
                acc[3][1] = fma2(wp23.y, h1, acc[3][1]);
                acc[3][2] = fma2(wp23.y, h2, acc[3][2]);
                acc[3][3] = fma2(wp23.y, h3, acc[3][3]);
            }
        }

        // combine ksub halves (lane ^ 16 has same tile)
#pragma unroll
        for (int cp = 0; cp < 4; cp++)
#pragma unroll
            for (int j = 0; j < 4; j++)
                acc[cp][j] = add2(acc[cp][j],
                                  __shfl_xor_sync(0xFFFFFFFFu, acc[cp][j], 16));

        // lanes ksub=0 store partials: red[w][b*36 + c], STS.128 per (j, cph)
        if (ksub == 0) {
            float* rw = red + w * 576;
#pragma unroll
            for (int j = 0; j < 4; j++) {
                int b_loc = (bq << 2) + j;
#pragma unroll
                for (int cph = 0; cph < 2; cph++) {
                    ulonglong2 v;
                    v.x = acc[2 * cph][j];
                    v.y = acc[2 * cph + 1][j];
                    *(ulonglong2*)&rw[b_loc * 36 + (cq << 3) + (cph << 2)] = v;
                }
            }
        }
        BARX(1);

        // reduce 8 partials, tanh, write next h (b-pair per thread)
        float sx = 0.0f, sy = 0.0f;
#pragma unroll
        for (int ww = 0; ww < 8; ww++) {
            sx += red[ww * 576 + b2 * 36 + c_l];
            sy += red[ww * 576 + (b2 + 1) * 36 + c_l];
        }
        float hv0 = tanhf(xp0 + sx);
        float hv1 = tanhf(xp1 + sy);
        __stcg((float2*)(hdst + c_g * Bb + B0 + b2), make_float2(hv0, hv1));

        BARX(1);   // h stores HB-before t0's release; also guards red reuse
        if (t == 0 && step < Tt - 1) {
            arrive_release(cnt);
            unsigned target = 32u * (unsigned)(step + 1);
            while (ld_acquire(cnt) < target) { }
            int nb = (step + 1) >> 5;
            while (ld_acquire(&g_xcnt[nb]) < XP_TILES_PER_BLK) { }
        }
        // out writes overlap t0's spin
        __stcg(out + xi0, hv0);
        __stcg(out + xi1, hv1);
        if (step == Tt - 1) {
            out[Bb * Tt * Hh + (B0 + b2) * Hh + c_g] = hv0;
            out[Bb * Tt * Hh + (B0 + b2 + 1) * Hh + c_g] = hv1;
        }
        xi0 += Hh; xi1 += Hh;
        BARX(1);
    }
}

// ---------------------------------------------------------------------------
// Fused persistent kernel (structure unchanged from R12 winner).
// ---------------------------------------------------------------------------
__global__ void __launch_bounds__(512, 1) regrnn_fused(
    const float* __restrict__ seq,
    const float* __restrict__ w_hh, const float* __restrict__ w_hh_mask,
    float* __restrict__ out)
{
    extern __shared__ __align__(16) float sm[];
    const int t = threadIdx.x;
    const int cta = blockIdx.x;
    const int half = t >> 8;
    const int rtid = t & 255;

    float* xpB_As = sm + RNN_FLOATS;
    float* xpB_Bs = xpB_As + 16 * 132;
    float* xpA_As = sm;
    float* xpA_Bs = xpA_As + 16 * 132;

    if (cta < FUSED_CTAS) {
        if (half == 0) {
            rnn_role(rtid, cta, w_hh, w_hh_mask, out, sm);
        } else {
            xproj_role(rtid, 2, xpB_As, xpB_Bs, cta, seq, out);
        }
    } else {
        if (half == 0) {
            xproj_role(rtid, 1, xpA_As, xpA_Bs, FUSED_CTAS + (cta - FUSED_CTAS) * 2, seq, out);
        } else {
            xproj_role(rtid, 2, xpB_As, xpB_Bs, FUSED_CTAS + (cta - FUSED_CTAS) * 2 + 1, seq, out);
        }
    }

    // exit protocol: last CTA resets all counters for next graph replay
    if (t == 0) {
        __threadfence();
        unsigned old = atomicAdd(&g_done, 1u);
        if (old == TOTAL_CTAS - 1) {
#pragma unroll 8
            for (int i = 0; i < 128; i++) g_cnt[i] = 0u;
#pragma unroll
            for (int i = 0; i < XP_BLKS; i++) g_xcnt[i] = 0u;
            __threadfence();
            g_done = 0u;
        }
    }
}

// ---------------------------------------------------------------------------
extern "C" void kernel_launch(void* const* d_in, const int* in_sizes, int n_in,
                              void* d_out, int out_size) {
    (void)in_sizes; (void)n_in; (void)out_size;
    const float* seq       = (const float*)d_in[0];
    const float* w_ih      = (const float*)d_in[1];
    const float* w_ih_mask = (const float*)d_in[2];
    const float* w_hh      = (const float*)d_in[3];
    const float* w_hh_mask = (const float*)d_in[4];
    const float* b_ih      = (const float*)d_in[5];
    const float* b_ih_mask = (const float*)d_in[6];
    const float* b_hh      = (const float*)d_in[7];
    const float* b_hh_mask = (const float*)d_in[8];
    float* out = (float*)d_out;

    regrnn_prep<<<(Hh * Ii + 255) / 256, 256>>>(w_ih, w_ih_mask,
                                                b_ih, b_ih_mask, b_hh, b_hh_mask);

    cudaFuncSetAttribute(regrnn_fused, cudaFuncAttributeMaxDynamicSharedMemorySize, SMEM_BYTES);
    regrnn_fused<<<TOTAL_CTAS, 512, SMEM_BYTES>>>(seq, w_hh, w_hh_mask, out);
}